// round 2
// baseline (speedup 1.0000x reference)
#include <cuda_runtime.h>

// Problem constants (static per reference)
#define A_N    900      // anchors
#define P_N    13       // points
#define CAM_N  6        // cameras
#define LVL_N  4        // levels
#define CH     256      // channels
#define G_N    8        // groups (32 ch each)
#define SAMP   (P_N * CAM_N * LVL_N)   // 312 samples per anchor
#define THW    14960    // sum of H*W over levels

__constant__ int   c_H[LVL_N] = {64, 32, 16, 8};
__constant__ int   c_W[LVL_N] = {176, 88, 44, 22};
__constant__ int   c_S[LVL_N] = {0, 11264, 14080, 14784};

// grid = (900, 2): blockIdx.x = anchor, blockIdx.y = channel half (128 ch each)
// block = 128 threads: 4 warps = 4 sample-lanes, each warp's 32 threads own one
// float4 channel quad of this half -> every corner gather is a fully coalesced
// 512B (32 x LDG.128) burst from one feature row.
__global__ __launch_bounds__(128)
void daf_kernel(const float* __restrict__ feature,   // [1,6,14960,256]
                const float* __restrict__ points,    // [1,900,13,6,2]
                const float* __restrict__ weights,   // [1,900,13,6,4,8]
                float* __restrict__ out)             // [1,900,256]
{
    const int a    = blockIdx.x;
    const int half = blockIdx.y;          // 0 or 1
    const int tid  = threadIdx.x;

    __shared__ int    s_idx[SAMP][4];   // absolute row index per corner (clamped)
    __shared__ float  s_cw [SAMP][4];   // bilinear weight * validity
    __shared__ float  s_w  [SAMP][G_N]; // per-group attention weight
    __shared__ float4 s_red[128];       // cross-lane reduction buffer

    // ---------- Phase 1: per-sample metadata ----------
    for (int s = tid; s < SAMP; s += 128) {
        const int pt  = s / (CAM_N * LVL_N);
        const int rem = s - pt * (CAM_N * LVL_N);
        const int cam = rem / LVL_N;
        const int lvl = rem - cam * LVL_N;

        const float2 p = *reinterpret_cast<const float2*>(
            points + (((size_t)a * P_N + pt) * CAM_N + cam) * 2);

        const int h = c_H[lvl], w = c_W[lvl];
        const float x = p.x * (float)w - 0.5f;
        const float y = p.y * (float)h - 0.5f;
        const float x0f = floorf(x), y0f = floorf(y);
        const int   x0  = (int)x0f,  y0  = (int)y0f;
        const float fx  = x - x0f,   fy  = y - y0f;
        const float wx[2] = {1.0f - fx, fx};
        const float wy[2] = {1.0f - fy, fy};
        const int base = cam * THW + c_S[lvl];

        #pragma unroll
        for (int k = 0; k < 4; k++) {
            const int dx = k & 1, dy = k >> 1;
            const int xi = x0 + dx, yi = y0 + dy;
            const bool valid = (xi >= 0) & (xi < w) & (yi >= 0) & (yi < h);
            const int xc = min(max(xi, 0), w - 1);
            const int yc = min(max(yi, 0), h - 1);
            s_idx[s][k] = base + yc * w + xc;
            s_cw [s][k] = valid ? wx[dx] * wy[dy] : 0.0f;
        }

        const float* wp = weights + ((((size_t)a * P_N + pt) * CAM_N + cam) * LVL_N + lvl) * G_N;
        #pragma unroll
        for (int g = 0; g < G_N; g++) s_w[s][g] = wp[g];
    }
    __syncthreads();

    // ---------- Phase 2: gather + weighted accumulate ----------
    const int lane = tid & 31;              // channel quad within this half
    const int sub  = tid >> 5;              // sample lane 0..3 (= warp id)
    const int coff = half * 128 + lane * 4; // global channel offset of this quad
    const int g    = coff >> 5;             // group of this quad

    float4 acc = make_float4(0.f, 0.f, 0.f, 0.f);

    #pragma unroll 2
    for (int s = sub; s < SAMP; s += 4) {
        const int i0 = s_idx[s][0], i1 = s_idx[s][1];
        const int i2 = s_idx[s][2], i3 = s_idx[s][3];
        const float cw0 = s_cw[s][0], cw1 = s_cw[s][1];
        const float cw2 = s_cw[s][2], cw3 = s_cw[s][3];
        const float wg  = s_w[s][g];

        const float4 f0 = *reinterpret_cast<const float4*>(feature + (size_t)i0 * CH + coff);
        const float4 f1 = *reinterpret_cast<const float4*>(feature + (size_t)i1 * CH + coff);
        const float4 f2 = *reinterpret_cast<const float4*>(feature + (size_t)i2 * CH + coff);
        const float4 f3 = *reinterpret_cast<const float4*>(feature + (size_t)i3 * CH + coff);

        float vx = cw0 * f0.x + cw1 * f1.x + cw2 * f2.x + cw3 * f3.x;
        float vy = cw0 * f0.y + cw1 * f1.y + cw2 * f2.y + cw3 * f3.y;
        float vz = cw0 * f0.z + cw1 * f1.z + cw2 * f2.z + cw3 * f3.z;
        float vw = cw0 * f0.w + cw1 * f1.w + cw2 * f2.w + cw3 * f3.w;

        acc.x += wg * vx;
        acc.y += wg * vy;
        acc.z += wg * vz;
        acc.w += wg * vw;
    }

    // ---------- Phase 3: reduce 4 sample-lanes ----------
    s_red[tid] = acc;
    __syncthreads();

    if (sub == 0) {
        float4 r0 = s_red[lane];
        float4 r1 = s_red[32 + lane];
        float4 r2 = s_red[64 + lane];
        float4 r3 = s_red[96 + lane];
        float4 r;
        r.x = r0.x + r1.x + r2.x + r3.x;
        r.y = r0.y + r1.y + r2.y + r3.y;
        r.z = r0.z + r1.z + r2.z + r3.z;
        r.w = r0.w + r1.w + r2.w + r3.w;
        *reinterpret_cast<float4*>(out + (size_t)a * CH + coff) = r;
    }
}

extern "C" void kernel_launch(void* const* d_in, const int* in_sizes, int n_in,
                              void* d_out, int out_size)
{
    const float* feature = (const float*)d_in[0];
    // d_in[1] = spatial_shapes, d_in[2] = level_start_index (static, hardcoded)
    const float* points  = (const float*)d_in[3];
    const float* weights = (const float*)d_in[4];
    float* out = (float*)d_out;

    dim3 grid(A_N, 2);
    daf_kernel<<<grid, 128>>>(feature, points, weights, out);
}

// round 3
// speedup vs baseline: 1.0257x; 1.0257x over previous
#include <cuda_runtime.h>

// Problem constants (static per reference)
#define A_N    900      // anchors
#define P_N    13       // points
#define CAM_N  6        // cameras
#define LVL_N  4        // levels
#define CH     256      // channels
#define G_N    8        // groups (32 ch each)
#define SAMP   (P_N * CAM_N * LVL_N)   // 312 samples per anchor
#define THW    14960    // sum of H*W over levels

__constant__ int   c_H[LVL_N] = {64, 32, 16, 8};
__constant__ int   c_W[LVL_N] = {176, 88, 44, 22};
__constant__ int   c_S[LVL_N] = {0, 11264, 14080, 14784};

// One CTA per anchor, 256 threads = 4 sample-lanes x 64 channel-quad lanes.
// __launch_bounds__(256, 5): cap regs ~51 so 5 CTAs fit per SM (40 warps)
// instead of 4 (32 warps) -> more outstanding LDG.128 to hide L2 latency.
__global__ __launch_bounds__(256, 5)
void daf_kernel(const float* __restrict__ feature,   // [1,6,14960,256]
                const float* __restrict__ points,    // [1,900,13,6,2]
                const float* __restrict__ weights,   // [1,900,13,6,4,8]
                float* __restrict__ out)             // [1,900,256]
{
    const int a   = blockIdx.x;
    const int tid = threadIdx.x;

    __shared__ int    s_idx[SAMP][4];   // absolute row index per corner (clamped)
    __shared__ float  s_cw [SAMP][4];   // bilinear weight * validity
    __shared__ float  s_w  [SAMP][G_N]; // per-group attention weight
    __shared__ float4 s_red[256];       // cross-lane reduction buffer

    // ---------- Phase 1: per-sample metadata ----------
    for (int s = tid; s < SAMP; s += 256) {
        const int pt  = s / (CAM_N * LVL_N);
        const int rem = s - pt * (CAM_N * LVL_N);
        const int cam = rem / LVL_N;
        const int lvl = rem - cam * LVL_N;

        const float2 p = *reinterpret_cast<const float2*>(
            points + (((size_t)a * P_N + pt) * CAM_N + cam) * 2);

        const int h = c_H[lvl], w = c_W[lvl];
        const float x = p.x * (float)w - 0.5f;
        const float y = p.y * (float)h - 0.5f;
        const float x0f = floorf(x), y0f = floorf(y);
        const int   x0  = (int)x0f,  y0  = (int)y0f;
        const float fx  = x - x0f,   fy  = y - y0f;
        const float wx[2] = {1.0f - fx, fx};
        const float wy[2] = {1.0f - fy, fy};
        const int base = cam * THW + c_S[lvl];

        #pragma unroll
        for (int k = 0; k < 4; k++) {
            const int dx = k & 1, dy = k >> 1;
            const int xi = x0 + dx, yi = y0 + dy;
            const bool valid = (xi >= 0) & (xi < w) & (yi >= 0) & (yi < h);
            const int xc = min(max(xi, 0), w - 1);
            const int yc = min(max(yi, 0), h - 1);
            s_idx[s][k] = base + yc * w + xc;
            s_cw [s][k] = valid ? wx[dx] * wy[dy] : 0.0f;
        }

        // weights for this sample: 8 contiguous floats -> two float4 copies
        const float4* wp = reinterpret_cast<const float4*>(
            weights + ((((size_t)a * P_N + pt) * CAM_N + cam) * LVL_N + lvl) * G_N);
        float4* wd = reinterpret_cast<float4*>(&s_w[s][0]);
        wd[0] = wp[0];
        wd[1] = wp[1];
    }
    __syncthreads();

    // ---------- Phase 2: gather + weighted accumulate ----------
    // 4 sample-lanes of 64 threads; each thread owns a float4 channel quad.
    const int lane = tid & 63;        // channel quad id: channels [lane*4, lane*4+3]
    const int sub  = tid >> 6;        // sample lane 0..3
    const int g    = lane >> 3;       // group of this channel quad (32 ch / group)

    float4 acc = make_float4(0.f, 0.f, 0.f, 0.f);

    #pragma unroll 2
    for (int s = sub; s < SAMP; s += 4) {
        const int i0 = s_idx[s][0], i1 = s_idx[s][1];
        const int i2 = s_idx[s][2], i3 = s_idx[s][3];
        const float cw0 = s_cw[s][0], cw1 = s_cw[s][1];
        const float cw2 = s_cw[s][2], cw3 = s_cw[s][3];
        const float wg  = s_w[s][g];

        const float4 f0 = *reinterpret_cast<const float4*>(feature + (size_t)i0 * CH + lane * 4);
        const float4 f1 = *reinterpret_cast<const float4*>(feature + (size_t)i1 * CH + lane * 4);
        const float4 f2 = *reinterpret_cast<const float4*>(feature + (size_t)i2 * CH + lane * 4);
        const float4 f3 = *reinterpret_cast<const float4*>(feature + (size_t)i3 * CH + lane * 4);

        float vx = cw0 * f0.x + cw1 * f1.x + cw2 * f2.x + cw3 * f3.x;
        float vy = cw0 * f0.y + cw1 * f1.y + cw2 * f2.y + cw3 * f3.y;
        float vz = cw0 * f0.z + cw1 * f1.z + cw2 * f2.z + cw3 * f3.z;
        float vw = cw0 * f0.w + cw1 * f1.w + cw2 * f2.w + cw3 * f3.w;

        acc.x += wg * vx;
        acc.y += wg * vy;
        acc.z += wg * vz;
        acc.w += wg * vw;
    }

    // ---------- Phase 3: reduce 4 sample-lanes ----------
    s_red[tid] = acc;
    __syncthreads();

    if (sub == 0) {
        float4 r0 = s_red[lane];
        float4 r1 = s_red[64 + lane];
        float4 r2 = s_red[128 + lane];
        float4 r3 = s_red[192 + lane];
        float4 r;
        r.x = r0.x + r1.x + r2.x + r3.x;
        r.y = r0.y + r1.y + r2.y + r3.y;
        r.z = r0.z + r1.z + r2.z + r3.z;
        r.w = r0.w + r1.w + r2.w + r3.w;
        *reinterpret_cast<float4*>(out + (size_t)a * CH + lane * 4) = r;
    }
}

extern "C" void kernel_launch(void* const* d_in, const int* in_sizes, int n_in,
                              void* d_out, int out_size)
{
    const float* feature = (const float*)d_in[0];
    // d_in[1] = spatial_shapes, d_in[2] = level_start_index (static, hardcoded)
    const float* points  = (const float*)d_in[3];
    const float* weights = (const float*)d_in[4];
    float* out = (float*)d_out;

    daf_kernel<<<A_N, 256>>>(feature, points, weights, out);
}

// round 4
// speedup vs baseline: 1.4672x; 1.4305x over previous
#include <cuda_runtime.h>

// Problem constants (static per reference)
#define A_N    900      // anchors
#define P_N    13       // points
#define CAM_N  6        // cameras
#define LVL_N  4        // levels
#define CH     256      // channels
#define G_N    8        // groups (32 ch each)
#define SAMP   (P_N * CAM_N * LVL_N)   // 312 samples per anchor
#define THW    14960    // sum of H*W over levels
#define SPLIT  2
#define SPC    (SAMP / SPLIT)          // 156 samples per CTA

__constant__ int c_H[LVL_N] = {64, 32, 16, 8};
__constant__ int c_W[LVL_N] = {176, 88, 44, 22};
__constant__ int c_S[LVL_N] = {0, 11264, 14080, 14784};

// Partial sums: [SPLIT][A_N][CH]
__device__ float d_partial[SPLIT * A_N * CH];

// grid = (900, 2): blockIdx.x = anchor, blockIdx.y = sample half.
// 256 threads = 8 warps; each warp processes whole samples (all 256 channels):
// lane owns channel quads [lane*4, lane*4+4) and [128+lane*4, 128+lane*4+4).
// => 8 independent LDG.128 per sample iteration (4 corners x 2 quads).
__global__ __launch_bounds__(256, 4)
void daf_gather(const float* __restrict__ feature,   // [1,6,14960,256]
                const float* __restrict__ points,    // [1,900,13,6,2]
                const float* __restrict__ weights)   // [1,900,13,6,4,8]
{
    const int a   = blockIdx.x;
    const int hlf = blockIdx.y;
    const int tid = threadIdx.x;

    __shared__ int4   s_idx[SPC];       // 4 corner row indices
    __shared__ float4 s_cw [SPC];       // 4 bilinear*valid weights
    __shared__ float  s_w  [SPC][G_N];  // 8 group weights
    __shared__ float  s_red[8][CH];     // per-warp partials

    // ---------- Phase 1: metadata for THIS CTA's 156 samples only ----------
    for (int i = tid; i < SPC; i += 256) {
        const int s   = hlf * SPC + i;
        const int pt  = s / (CAM_N * LVL_N);
        const int rem = s - pt * (CAM_N * LVL_N);
        const int cam = rem >> 2;            // / LVL_N
        const int lvl = rem & 3;             // % LVL_N

        const float2 p = *reinterpret_cast<const float2*>(
            points + (((size_t)a * P_N + pt) * CAM_N + cam) * 2);

        const int h = c_H[lvl], w = c_W[lvl];
        const float x = p.x * (float)w - 0.5f;
        const float y = p.y * (float)h - 0.5f;
        const float x0f = floorf(x), y0f = floorf(y);
        const int   x0  = (int)x0f,  y0  = (int)y0f;
        const float fx  = x - x0f,   fy  = y - y0f;
        const float wx[2] = {1.0f - fx, fx};
        const float wy[2] = {1.0f - fy, fy};
        const int base = cam * THW + c_S[lvl];

        int   vi[4];
        float vc[4];
        #pragma unroll
        for (int k = 0; k < 4; k++) {
            const int dx = k & 1, dy = k >> 1;
            const int xi = x0 + dx, yi = y0 + dy;
            const bool valid = (xi >= 0) & (xi < w) & (yi >= 0) & (yi < h);
            const int xc = min(max(xi, 0), w - 1);
            const int yc = min(max(yi, 0), h - 1);
            vi[k] = base + yc * w + xc;
            vc[k] = valid ? wx[dx] * wy[dy] : 0.0f;
        }
        s_idx[i] = make_int4(vi[0], vi[1], vi[2], vi[3]);
        s_cw [i] = make_float4(vc[0], vc[1], vc[2], vc[3]);

        const float4* wp = reinterpret_cast<const float4*>(
            weights + ((((size_t)a * P_N + pt) * CAM_N + cam) * LVL_N + lvl) * G_N);
        float4* wd = reinterpret_cast<float4*>(&s_w[i][0]);
        wd[0] = wp[0];
        wd[1] = wp[1];
    }
    __syncthreads();

    // ---------- Phase 2: gather + weighted accumulate ----------
    const int warp = tid >> 5;
    const int lane = tid & 31;
    const int g    = lane >> 3;   // group of quad A (quad B is group 4+g)

    float4 accA = make_float4(0.f, 0.f, 0.f, 0.f);
    float4 accB = make_float4(0.f, 0.f, 0.f, 0.f);

    for (int i = warp; i < SPC; i += 8) {
        const int4   idx = s_idx[i];
        const float4 cw  = s_cw[i];
        const float  wgA = s_w[i][g];
        const float  wgB = s_w[i][4 + g];

        const float4* r0 = reinterpret_cast<const float4*>(feature + (size_t)idx.x * CH) + lane;
        const float4* r1 = reinterpret_cast<const float4*>(feature + (size_t)idx.y * CH) + lane;
        const float4* r2 = reinterpret_cast<const float4*>(feature + (size_t)idx.z * CH) + lane;
        const float4* r3 = reinterpret_cast<const float4*>(feature + (size_t)idx.w * CH) + lane;

        // 8 independent vector loads (4 corners x 2 channel quads)
        const float4 a0 = r0[0],  b0 = r0[32];
        const float4 a1 = r1[0],  b1 = r1[32];
        const float4 a2 = r2[0],  b2 = r2[32];
        const float4 a3 = r3[0],  b3 = r3[32];

        float4 vA, vB;
        vA.x = cw.x*a0.x + cw.y*a1.x + cw.z*a2.x + cw.w*a3.x;
        vA.y = cw.x*a0.y + cw.y*a1.y + cw.z*a2.y + cw.w*a3.y;
        vA.z = cw.x*a0.z + cw.y*a1.z + cw.z*a2.z + cw.w*a3.z;
        vA.w = cw.x*a0.w + cw.y*a1.w + cw.z*a2.w + cw.w*a3.w;
        vB.x = cw.x*b0.x + cw.y*b1.x + cw.z*b2.x + cw.w*b3.x;
        vB.y = cw.x*b0.y + cw.y*b1.y + cw.z*b2.y + cw.w*b3.y;
        vB.z = cw.x*b0.z + cw.y*b1.z + cw.z*b2.z + cw.w*b3.z;
        vB.w = cw.x*b0.w + cw.y*b1.w + cw.z*b2.w + cw.w*b3.w;

        accA.x += wgA * vA.x;  accA.y += wgA * vA.y;
        accA.z += wgA * vA.z;  accA.w += wgA * vA.w;
        accB.x += wgB * vB.x;  accB.y += wgB * vB.y;
        accB.z += wgB * vB.z;  accB.w += wgB * vB.w;
    }

    // ---------- Phase 3: reduce 8 warps, write partial ----------
    reinterpret_cast<float4*>(&s_red[warp][0])[lane]       = accA;
    reinterpret_cast<float4*>(&s_red[warp][0])[32 + lane]  = accB;
    __syncthreads();

    if (tid < 64) {
        float4 r = make_float4(0.f, 0.f, 0.f, 0.f);
        #pragma unroll
        for (int w = 0; w < 8; w++) {
            const float4 t = reinterpret_cast<const float4*>(&s_red[w][0])[tid];
            r.x += t.x; r.y += t.y; r.z += t.z; r.w += t.w;
        }
        reinterpret_cast<float4*>(
            d_partial + ((size_t)hlf * A_N + a) * CH)[tid] = r;
    }
}

// Sum the two sample-half partials into the output. grid 900 x 256 = 230400.
__global__ void daf_reduce(float* __restrict__ out)
{
    const int i = blockIdx.x * 256 + threadIdx.x;
    out[i] = d_partial[i] + d_partial[A_N * CH + i];
}

extern "C" void kernel_launch(void* const* d_in, const int* in_sizes, int n_in,
                              void* d_out, int out_size)
{
    const float* feature = (const float*)d_in[0];
    // d_in[1] = spatial_shapes, d_in[2] = level_start_index (static, hardcoded)
    const float* points  = (const float*)d_in[3];
    const float* weights = (const float*)d_in[4];
    float* out = (float*)d_out;

    dim3 grid(A_N, SPLIT);
    daf_gather<<<grid, 256>>>(feature, points, weights);
    daf_reduce<<<A_N, 256>>>(out);
}